// round 16
// baseline (speedup 1.0000x reference)
#include <cuda_runtime.h>
#include <cstddef>

#define BATCH 16
#define NN 128
#define DD 128
#define EE 64
#define HH 256
#define ROWS (BATCH*NN)   // 2048
#define EPSLN 1e-5f

#define GRELU 1
#define GMASK 2

// ---------------- scratch (static device buffers, no allocation) ----------------
__device__ float g_x[ROWS*DD];
__device__ float g_np[ROWS*HH];
__device__ float g_s[ROWS*HH];
__device__ float g_u1[ROWS*HH];
__device__ float g_cnt[ROWS];
__device__ float g_uwc[3*384*HH];   // per layer: [uw1a(128) ; w2@uw1b(256)] x 256
__device__ float g_bb[3*HH];        // per layer: b2 @ uw1b

// ---------------- helpers ----------------
__device__ __forceinline__ unsigned f2tf(float f) {
    unsigned r;
    asm("cvt.rna.tf32.f32 %0, %1;" : "=r"(r) : "f"(f));
    return r;
}

__device__ __forceinline__ void tfsplit(float v, unsigned& hi, unsigned& lo) {
    hi = f2tf(v);
    lo = f2tf(v - __uint_as_float(hi));
}

__device__ __forceinline__ void mma_tf32(float* d,
                                         unsigned a0, unsigned a1, unsigned a2, unsigned a3,
                                         unsigned b0, unsigned b1) {
    asm volatile("mma.sync.aligned.m16n8k8.row.col.f32.tf32.tf32.f32 "
                 "{%0,%1,%2,%3}, {%4,%5,%6,%7}, {%8,%9}, {%0,%1,%2,%3};"
                 : "+f"(d[0]), "+f"(d[1]), "+f"(d[2]), "+f"(d[3])
                 : "r"(a0), "r"(a1), "r"(a2), "r"(a3), "r"(b0), "r"(b1));
}

__device__ __forceinline__ unsigned pk_bf2(float lo, float hi) {
    unsigned d;
    asm("cvt.rn.bf16x2.f32 %0, %1, %2;" : "=r"(d) : "f"(hi), "f"(lo));
    return d;
}

__device__ __forceinline__ void mma_bf16(float* d,
                                         unsigned a0, unsigned a1, unsigned a2, unsigned a3,
                                         unsigned b0, unsigned b1) {
    asm volatile("mma.sync.aligned.m16n8k16.row.col.f32.bf16.bf16.f32 "
                 "{%0,%1,%2,%3}, {%4,%5,%6,%7}, {%8,%9}, {%0,%1,%2,%3};"
                 : "+f"(d[0]), "+f"(d[1]), "+f"(d[2]), "+f"(d[3])
                 : "r"(a0), "r"(a1), "r"(a2), "r"(a3), "r"(b0), "r"(b1));
}

// ---------------- prep: x = nodes * mask (float4) ----------------
__global__ void prep_x_kernel(const float* __restrict__ nodes,
                              const int* __restrict__ mask,
                              float* __restrict__ x) {
    int idx = blockIdx.x * 256 + threadIdx.x;
    int row = idx >> 5;
    float mi = mask[row] ? 1.f : 0.f;
    float4 v = ((const float4*)nodes)[idx];
    v.x *= mi; v.y *= mi; v.z *= mi; v.w *= mi;
    ((float4*)x)[idx] = v;
}

// cnt[b*N+i] = mask[b,i] * sum_j mask[b,j]
__global__ void prep_cnt_kernel(const int* __restrict__ mask,
                                float* __restrict__ cnt) {
    int b = blockIdx.x;
    int j = threadIdx.x;
    __shared__ float red[NN];
    float m = mask[b*NN + j] ? 1.f : 0.f;
    red[j] = m;
    __syncthreads();
    for (int s2 = 64; s2 > 0; s2 >>= 1) {
        if (j < s2) red[j] += red[j + s2];
        __syncthreads();
    }
    cnt[b*NN + j] = m * red[0];
}

// ---------------- copy uw1a rows into combined weight (float4) ----------------
__global__ void copy_uwc_kernel(const float* __restrict__ upd_w1,
                                float* __restrict__ uwc) {
    int l = blockIdx.y;
    int g = blockIdx.x * 256 + threadIdx.x;
    ((float4*)uwc)[(size_t)l*24576 + g] = ((const float4*)upd_w1)[(size_t)l*24576 + g];
}

// bb[l][n] = sum_k b2[l][k] * uw1[l][128+k][n]
__global__ void bb_kernel(const float* __restrict__ msg_b2,
                          const float* __restrict__ upd_w1,
                          float* __restrict__ bb) {
    int n = blockIdx.x;
    int l = blockIdx.y;
    int k = threadIdx.x;
    __shared__ float red[HH];
    red[k] = msg_b2[l*HH + k] * upd_w1[(size_t)l*384*HH + (128 + k)*HH + n];
    __syncthreads();
    for (int s2 = 128; s2 > 0; s2 >>= 1) {
        if (k < s2) red[k] += red[k + s2];
        __syncthreads();
    }
    if (k == 0) bb[l*HH + n] = red[0];
}

// ---------------- bf16 tensor-core edge kernel, 512 threads ----------------
// s[b,i,h] = m_i * sum_j m_j * relu( np[b,i,h] + b1[h] + sum_e E[j,e]*W[e,h] )
// 16 warps, each owning 16 h-columns (NT=2) -> ~52 core regs, capped at 64
// via launch_bounds(512,2) => 32 warps/SM (vs 16 before) for latency hiding.
__global__ __launch_bounds__(512, 2)
void edge_msg_tc(const float* __restrict__ edges,
                 const float* __restrict__ We,    // (64,256)
                 const float* __restrict__ b1,    // (256)
                 const float* __restrict__ np,    // (ROWS,256)
                 const int* __restrict__ mask,
                 float* __restrict__ s_out) {
    __shared__ __align__(16) unsigned sE[128 * 36];  // bf16x2 words, stride 36
    __shared__ float smj[NN];

    int row = blockIdx.x;
    int b = row >> 7;
    int t = threadIdx.x;
    int w = t >> 5;                  // 0..15
    int lane = t & 31;
    int hb = w * 16;                 // 16 h-cols per warp
    int r = lane >> 2;
    int c = lane & 3;

    // ---- stage E tile (128 j-rows x 64 e) as packed bf16 pairs ----
    const float4* src = (const float4*)(edges + (size_t)row * NN * EE);
#pragma unroll
    for (int g = t; g < 2048; g += 512) {
        float4 v = src[g];
        int rr = g >> 4;
        int p0 = (g & 15) * 2;
        unsigned w0 = pk_bf2(v.x, v.y);
        unsigned w1 = pk_bf2(v.z, v.w);
        *(uint2*)&sE[rr * 36 + p0] = make_uint2(w0, w1);
    }
    if (t < NN) smj[t] = mask[b*NN + t] ? 1.f : 0.f;

    // ---- B fragments (NT=2) ----
    unsigned B0[2][4], B1[2][4];
#pragma unroll
    for (int nt = 0; nt < 2; nt++) {
        int col = hb + nt*8 + r;
#pragma unroll
        for (int kk = 0; kk < 4; kk++) {
            int e0 = kk*16 + 2*c;
            B0[nt][kk] = pk_bf2(We[(e0)     * HH + col], We[(e0 + 1) * HH + col]);
            B1[nt][kk] = pk_bf2(We[(e0 + 8) * HH + col], We[(e0 + 9) * HH + col]);
        }
    }

    float npv0[2], npv1[2];
#pragma unroll
    for (int nt = 0; nt < 2; nt++) {
        int h = hb + nt*8 + 2*c;
        npv0[nt] = np[(size_t)row*HH + h]     + b1[h];
        npv1[nt] = np[(size_t)row*HH + h + 1] + b1[h + 1];
    }

    float s0[2] = {0.f, 0.f};
    float s1[2] = {0.f, 0.f};

    __syncthreads();

#pragma unroll 1
    for (int m0 = 0; m0 < 8; m0++) {
        float acc[2][4];
#pragma unroll
        for (int nt = 0; nt < 2; nt++) {
            acc[nt][0] = 0.f; acc[nt][1] = 0.f; acc[nt][2] = 0.f; acc[nt][3] = 0.f;
        }
        int rbase0 = (m0*16 + r) * 36;
        int rbase1 = (m0*16 + r + 8) * 36;
#pragma unroll
        for (int kk = 0; kk < 4; kk++) {
            unsigned a0 = sE[rbase0 + kk*8 + c];
            unsigned a1 = sE[rbase1 + kk*8 + c];
            unsigned a2 = sE[rbase0 + kk*8 + c + 4];
            unsigned a3 = sE[rbase1 + kk*8 + c + 4];
#pragma unroll
            for (int nt = 0; nt < 2; nt++)
                mma_bf16(acc[nt], a0, a1, a2, a3, B0[nt][kk], B1[nt][kk]);
        }
        float mj0 = smj[m0*16 + r];
        float mj1 = smj[m0*16 + r + 8];
#pragma unroll
        for (int nt = 0; nt < 2; nt++) {
            s0[nt] += mj0 * fmaxf(acc[nt][0] + npv0[nt], 0.f)
                    + mj1 * fmaxf(acc[nt][2] + npv0[nt], 0.f);
            s1[nt] += mj0 * fmaxf(acc[nt][1] + npv1[nt], 0.f)
                    + mj1 * fmaxf(acc[nt][3] + npv1[nt], 0.f);
        }
    }

#pragma unroll
    for (int off = 4; off < 32; off <<= 1) {
#pragma unroll
        for (int nt = 0; nt < 2; nt++) {
            s0[nt] += __shfl_xor_sync(0xffffffffu, s0[nt], off);
            s1[nt] += __shfl_xor_sync(0xffffffffu, s1[nt], off);
        }
    }

    float mi = mask[row] ? 1.f : 0.f;
    if (lane < 4) {
#pragma unroll
        for (int nt = 0; nt < 2; nt++) {
            int h = hb + nt*8 + 2*lane;
            s_out[(size_t)row*HH + h]     = mi * s0[nt];
            s_out[(size_t)row*HH + h + 1] = mi * s1[nt];
        }
    }
}

// ---------------- 3xTF32 split tensor-core GEMM, 32x64 tiles, batched ---------
__global__ __launch_bounds__(128)
void gemm_tc(int M, int N, int K, int K1,
             const float* __restrict__ A, int lda,
             const float* __restrict__ A2, int lda2,
             const float* __restrict__ W, int ldw,
             const float* __restrict__ bias,
             const float* __restrict__ rowscale,
             const float* __restrict__ bias2,
             const int* __restrict__ maskrow,
             float* __restrict__ C, int ldc, int flags,
             size_t bsA, size_t bsW, size_t bsC) {
    __shared__ __align__(16) float sA[2][32 * 36];
    __shared__ __align__(16) float sB[2][32 * 72];

    A += bsA * blockIdx.z;
    W += bsW * blockIdx.z;
    C += bsC * blockIdx.z;

    int tid = threadIdx.x;
    int w = tid >> 5;
    int lane = tid & 31;
    int wm = w & 1, wn = w >> 1;
    int r = lane >> 2, c = lane & 3;

    int bm = blockIdx.y * 32, bn = blockIdx.x * 64;

    float acc[4][4];
#pragma unroll
    for (int nt = 0; nt < 4; nt++)
#pragma unroll
        for (int i = 0; i < 4; i++) acc[nt][i] = 0.f;

    float4 pa[2], pb[4];

#define PREFETCH(k0_) do {                                                   \
    _Pragma("unroll")                                                        \
    for (int q = 0; q < 2; q++) {                                            \
        int g = tid + q*128;                                                 \
        int row_ = g >> 3, col4 = (g & 7) * 4;                               \
        int gm = bm + row_, gk = (k0_) + col4;                               \
        if (A2 != nullptr && gk >= K1)                                       \
            pa[q] = *(const float4*)(A2 + (size_t)gm*lda2 + (gk - K1));      \
        else                                                                 \
            pa[q] = *(const float4*)(A + (size_t)gm*lda + gk);               \
    }                                                                        \
    _Pragma("unroll")                                                        \
    for (int q = 0; q < 4; q++) {                                            \
        int g = tid + q*128;                                                 \
        int row_ = g >> 4, col4 = (g & 15) * 4;                              \
        pb[q] = *(const float4*)(W + (size_t)((k0_) + row_)*ldw + bn + col4);\
    }                                                                        \
} while (0)

#define STORE_STAGE(s_) do {                                                 \
    _Pragma("unroll")                                                        \
    for (int q = 0; q < 2; q++) {                                            \
        int g = tid + q*128;                                                 \
        int row_ = g >> 3, col4 = (g & 7) * 4;                               \
        *(float4*)&sA[s_][row_*36 + col4] = pa[q];                           \
    }                                                                        \
    _Pragma("unroll")                                                        \
    for (int q = 0; q < 4; q++) {                                            \
        int g = tid + q*128;                                                 \
        int row_ = g >> 4, col4 = (g & 15) * 4;                              \
        *(float4*)&sB[s_][row_*72 + col4] = pb[q];                           \
    }                                                                        \
} while (0)

    PREFETCH(0);
    STORE_STAGE(0);
    __syncthreads();

    int s = 0;
    for (int k0 = 0; ; ) {
        bool haveNext = (k0 + 32 < K);
        if (haveNext) PREFETCH(k0 + 32);

#pragma unroll
        for (int kk = 0; kk < 4; kk++) {
            unsigned bh0[4], bl0[4], bh1[4], bl1[4];
#pragma unroll
            for (int nt = 0; nt < 4; nt++) {
                int col = wn*32 + nt*8 + r;
                tfsplit(sB[s][(kk*8 + c)     * 72 + col], bh0[nt], bl0[nt]);
                tfsplit(sB[s][(kk*8 + c + 4) * 72 + col], bh1[nt], bl1[nt]);
            }
            int row0 = (wm*16 + r) * 36;
            int row1 = (wm*16 + r + 8) * 36;
            unsigned ah0, al0, ah1, al1, ah2, al2, ah3, al3;
            tfsplit(sA[s][row0 + kk*8 + c],     ah0, al0);
            tfsplit(sA[s][row1 + kk*8 + c],     ah1, al1);
            tfsplit(sA[s][row0 + kk*8 + c + 4], ah2, al2);
            tfsplit(sA[s][row1 + kk*8 + c + 4], ah3, al3);
#pragma unroll
            for (int nt = 0; nt < 4; nt++) {
                mma_tf32(acc[nt], ah0, ah1, ah2, ah3, bh0[nt], bh1[nt]);
                mma_tf32(acc[nt], al0, al1, al2, al3, bh0[nt], bh1[nt]);
                mma_tf32(acc[nt], ah0, ah1, ah2, ah3, bl0[nt], bl1[nt]);
            }
        }

        k0 += 32;
        if (!haveNext) break;
        STORE_STAGE(s ^ 1);
        __syncthreads();
        s ^= 1;
    }
#undef PREFETCH
#undef STORE_STAGE

#pragma unroll
    for (int i2 = 0; i2 < 2; i2++) {
        int gm = bm + wm*16 + r + i2*8;
        float rs = (rowscale != nullptr) ? rowscale[gm] : 1.f;
        float mf = (flags & GMASK) ? (maskrow[gm] ? 1.f : 0.f) : 1.f;
#pragma unroll
        for (int nt = 0; nt < 4; nt++) {
#pragma unroll
            for (int j = 0; j < 2; j++) {
                int gn = bn + wn*32 + nt*8 + 2*c + j;
                float v = acc[nt][i2*2 + j];
                if (bias != nullptr) v += bias[gn];
                if (bias2 != nullptr) v += rs * bias2[gn];
                if (flags & GRELU) v = fmaxf(v, 0.f);
                v *= mf;
                C[(size_t)gm*ldc + gn] = v;
            }
        }
    }
}

// ---------------- fused u-GEMM + residual LayerNorm ----------------
__global__ __launch_bounds__(256)
void ugemm_ln(const float* __restrict__ u1,        // (ROWS,256)
              const float* __restrict__ uw2,       // (256,128)
              const float* __restrict__ ub2,       // (128)
              const int* __restrict__ mask,
              const float* __restrict__ lng,
              const float* __restrict__ lnb,
              float* __restrict__ x) {
    __shared__ __align__(16) float sA[2][16 * 36];
    __shared__ __align__(16) float sB[2][32 * 136];
    __shared__ float sU[16 * 132];

    int tid = threadIdx.x;
    int w = tid >> 5;
    int lane = tid & 31;
    int wn = w;
    int r = lane >> 2, c = lane & 3;
    int bm = blockIdx.x * 16;

    float acc[2][4];
#pragma unroll
    for (int nt = 0; nt < 2; nt++)
#pragma unroll
        for (int i = 0; i < 4; i++) acc[nt][i] = 0.f;

    float4 pa;  bool pav;
    float4 pb[4];

#define UPREFETCH(k0_) do {                                                  \
    pav = (tid < 128);                                                       \
    if (pav) {                                                               \
        int row_ = tid >> 3, col4 = (tid & 7) * 4;                           \
        pa = *(const float4*)(u1 + (size_t)(bm + row_)*HH + (k0_) + col4);   \
    }                                                                        \
    _Pragma("unroll")                                                        \
    for (int q = 0; q < 4; q++) {                                            \
        int g = tid + q*256;                                                 \
        int row_ = g >> 5, col4 = (g & 31) * 4;                              \
        pb[q] = *(const float4*)(uw2 + (size_t)((k0_) + row_)*DD + col4);    \
    }                                                                        \
} while (0)

#define USTORE(s_) do {                                                      \
    if (pav) {                                                               \
        int row_ = tid >> 3, col4 = (tid & 7) * 4;                           \
        *(float4*)&sA[s_][row_*36 + col4] = pa;                              \
    }                                                                        \
    _Pragma("unroll")                                                        \
    for (int q = 0; q < 4; q++) {                                            \
        int g = tid + q*256;                                                 \
        int row_ = g >> 5, col4 = (g & 31) * 4;                              \
        *(float4*)&sB[s_][row_*136 + col4] = pb[q];                          \
    }                                                                        \
} while (0)

    UPREFETCH(0);
    USTORE(0);
    __syncthreads();

    int s = 0;
    for (int k0 = 0; ; ) {
        bool haveNext = (k0 + 32 < HH);
        if (haveNext) UPREFETCH(k0 + 32);

#pragma unroll
        for (int kk = 0; kk < 4; kk++) {
            unsigned bh0[2], bl0[2], bh1[2], bl1[2];
#pragma unroll
            for (int nt = 0; nt < 2; nt++) {
                int col = wn*16 + nt*8 + r;
                tfsplit(sB[s][(kk*8 + c)     * 136 + col], bh0[nt], bl0[nt]);
                tfsplit(sB[s][(kk*8 + c + 4) * 136 + col], bh1[nt], bl1[nt]);
            }
            int row0 = r * 36;
            int row1 = (r + 8) * 36;
            unsigned ah0, al0, ah1, al1, ah2, al2, ah3, al3;
            tfsplit(sA[s][row0 + kk*8 + c],     ah0, al0);
            tfsplit(sA[s][row1 + kk*8 + c],     ah1, al1);
            tfsplit(sA[s][row0 + kk*8 + c + 4], ah2, al2);
            tfsplit(sA[s][row1 + kk*8 + c + 4], ah3, al3);
#pragma unroll
            for (int nt = 0; nt < 2; nt++) {
                mma_tf32(acc[nt], ah0, ah1, ah2, ah3, bh0[nt], bh1[nt]);
                mma_tf32(acc[nt], al0, al1, al2, al3, bh0[nt], bh1[nt]);
                mma_tf32(acc[nt], ah0, ah1, ah2, ah3, bl0[nt], bl1[nt]);
            }
        }

        k0 += 32;
        if (!haveNext) break;
        USTORE(s ^ 1);
        __syncthreads();
        s ^= 1;
    }
#undef UPREFETCH
#undef USTORE

#pragma unroll
    for (int i2 = 0; i2 < 2; i2++) {
        int rr = r + i2*8;
#pragma unroll
        for (int nt = 0; nt < 2; nt++) {
#pragma unroll
            for (int j = 0; j < 2; j++) {
                int col = wn*16 + nt*8 + 2*c + j;
                sU[rr*132 + col] = acc[nt][i2*2 + j] + ub2[col];
            }
        }
    }
    __syncthreads();

#pragma unroll
    for (int q0 = 0; q0 < 2; q0++) {
        int rr = w*2 + q0;
        int row = bm + rr;
        float mi = mask[row] ? 1.f : 0.f;
        float v[4];
#pragma unroll
        for (int q = 0; q < 4; q++) {
            int d = lane + q*32;
            v[q] = x[(size_t)row*DD + d] + sU[rr*132 + d] * mi;
        }
        float sum = v[0] + v[1] + v[2] + v[3];
#pragma unroll
        for (int o = 16; o > 0; o >>= 1) sum += __shfl_xor_sync(0xffffffffu, sum, o);
        float mu = sum * (1.f / DD);
        float var = 0.f;
#pragma unroll
        for (int q = 0; q < 4; q++) { float d2 = v[q] - mu; var += d2*d2; }
#pragma unroll
        for (int o = 16; o > 0; o >>= 1) var += __shfl_xor_sync(0xffffffffu, var, o);
        float rstd = rsqrtf(var * (1.f / DD) + EPSLN);
#pragma unroll
        for (int q = 0; q < 4; q++) {
            int d = lane + q*32;
            x[(size_t)row*DD + d] = ((v[q] - mu) * rstd * lng[d] + lnb[d]) * mi;
        }
    }
}

// ---------------- host launch ----------------
extern "C" void kernel_launch(void* const* d_in, const int* in_sizes, int n_in,
                              void* d_out, int out_size) {
    const float* nodes  = (const float*)d_in[0];
    const float* edges  = (const float*)d_in[1];
    const int*   mask   = (const int*)d_in[2];
    const float* msg_w1 = (const float*)d_in[3];
    const float* msg_b1 = (const float*)d_in[4];
    const float* msg_w2 = (const float*)d_in[5];
    const float* msg_b2 = (const float*)d_in[6];
    const float* upd_w1 = (const float*)d_in[7];
    const float* upd_b1 = (const float*)d_in[8];
    const float* upd_w2 = (const float*)d_in[9];
    const float* upd_b2 = (const float*)d_in[10];
    const float* ln_g   = (const float*)d_in[11];
    const float* ln_b   = (const float*)d_in[12];
    const float* out_w1 = (const float*)d_in[13];
    const float* out_b1 = (const float*)d_in[14];
    const float* out_w2 = (const float*)d_in[15];
    const float* out_b2 = (const float*)d_in[16];
    float* out = (float*)d_out;

    float *x, *np, *s, *u1, *cnt, *uwc, *bb;
    cudaGetSymbolAddress((void**)&x,   g_x);
    cudaGetSymbolAddress((void**)&np,  g_np);
    cudaGetSymbolAddress((void**)&s,   g_s);
    cudaGetSymbolAddress((void**)&u1,  g_u1);
    cudaGetSymbolAddress((void**)&cnt, g_cnt);
    cudaGetSymbolAddress((void**)&uwc, g_uwc);
    cudaGetSymbolAddress((void**)&bb,  g_bb);

    // ---- per-launch weight precompute (input-independent) ----
    copy_uwc_kernel<<<dim3(32, 3), 256>>>(upd_w1, uwc);
    gemm_tc<<<dim3(HH/64, 256/32, 3), 128>>>(256, HH, HH, 0,
        msg_w2, HH, nullptr, 0,
        upd_w1 + 128*HH, HH,
        nullptr, nullptr, nullptr, nullptr,
        uwc + 128*HH, HH, 0,
        (size_t)HH*HH, (size_t)384*HH, (size_t)384*HH);
    bb_kernel<<<dim3(HH, 3), 256>>>(msg_b2, upd_w1, bb);

    prep_x_kernel<<<256, 256>>>(nodes, mask, x);
    prep_cnt_kernel<<<BATCH, NN>>>(mask, cnt);

    for (int l = 0; l < 3; l++) {
        const float* w1n = msg_w1 + (size_t)l * 192 * HH;
        const float* w1e = w1n + (size_t)DD * HH;
        const float* b1  = msg_b1 + (size_t)l * HH;
        const float* ub1 = upd_b1 + (size_t)l * HH;
        const float* uw2 = upd_w2 + (size_t)l * HH * DD;
        const float* ub2 = upd_b2 + (size_t)l * DD;
        const float* lg  = ln_g + (size_t)l * DD;
        const float* lb  = ln_b + (size_t)l * DD;

        // np = x @ w1n
        gemm_tc<<<dim3(HH/64, ROWS/32), 128>>>(ROWS, HH, DD, 0,
            x, DD, nullptr, 0, w1n, HH, nullptr, nullptr, nullptr, nullptr,
            np, HH, 0, 0, 0, 0);

        // s = masked relu-reduce of (np + edges@w1e + b1)  [bf16 tensor cores]
        edge_msg_tc<<<ROWS, 512>>>(edges, w1e, b1, np, mask, s);

        // u1 = relu([x|s] @ [uw1a;W2u] + ub1 + cnt*bb)
        gemm_tc<<<dim3(HH/64, ROWS/32), 128>>>(ROWS, HH, DD + HH, DD,
            x, DD, s, HH, uwc + (size_t)l*384*HH, HH,
            ub1, cnt, bb + (size_t)l*HH, nullptr, u1, HH, GRELU, 0, 0, 0);

        // u = u1@uw2 + ub2 fused with x = LN(x + u*mi)*mi
        ugemm_ln<<<ROWS/16, 256>>>(u1, uw2, ub2, mask, lg, lb, x);
    }

    // z = relu(x @ out_w1 + out_b1) -> u1
    gemm_tc<<<dim3(HH/64, ROWS/32), 128>>>(ROWS, HH, DD, 0,
        x, DD, nullptr, 0, out_w1, HH, out_b1, nullptr, nullptr, nullptr,
        u1, HH, GRELU, 0, 0, 0);

    // out = (z @ out_w2 + out_b2) * mask
    gemm_tc<<<dim3(DD/64, ROWS/32), 128>>>(ROWS, DD, HH, 0,
        u1, HH, nullptr, 0, out_w2, DD, out_b2, nullptr, nullptr, mask,
        out, DD, GMASK, 0, 0, 0);
}

// round 17
// speedup vs baseline: 1.1127x; 1.1127x over previous
#include <cuda_runtime.h>
#include <cstddef>

#define BATCH 16
#define NN 128
#define DD 128
#define EE 64
#define HH 256
#define ROWS (BATCH*NN)   // 2048
#define EPSLN 1e-5f

#define GRELU 1
#define GMASK 2

// ---------------- scratch (static device buffers, no allocation) ----------------
__device__ float g_x[ROWS*DD];
__device__ float g_np[ROWS*HH];
__device__ float g_s[ROWS*HH];
__device__ float g_u1[ROWS*HH];
__device__ float g_cnt[ROWS];
__device__ float g_uwc[3*384*HH];   // per layer: [uw1a(128) ; w2@uw1b(256)] x 256
__device__ float g_bb[3*HH];        // per layer: b2 @ uw1b

// ---------------- helpers ----------------
__device__ __forceinline__ unsigned f2tf(float f) {
    unsigned r;
    asm("cvt.rna.tf32.f32 %0, %1;" : "=r"(r) : "f"(f));
    return r;
}

__device__ __forceinline__ void tfsplit(float v, unsigned& hi, unsigned& lo) {
    hi = f2tf(v);
    lo = f2tf(v - __uint_as_float(hi));
}

__device__ __forceinline__ void mma_tf32(float* d,
                                         unsigned a0, unsigned a1, unsigned a2, unsigned a3,
                                         unsigned b0, unsigned b1) {
    asm volatile("mma.sync.aligned.m16n8k8.row.col.f32.tf32.tf32.f32 "
                 "{%0,%1,%2,%3}, {%4,%5,%6,%7}, {%8,%9}, {%0,%1,%2,%3};"
                 : "+f"(d[0]), "+f"(d[1]), "+f"(d[2]), "+f"(d[3])
                 : "r"(a0), "r"(a1), "r"(a2), "r"(a3), "r"(b0), "r"(b1));
}

__device__ __forceinline__ unsigned pk_bf2(float lo, float hi) {
    unsigned d;
    asm("cvt.rn.bf16x2.f32 %0, %1, %2;" : "=r"(d) : "f"(hi), "f"(lo));
    return d;
}

__device__ __forceinline__ void mma_bf16(float* d,
                                         unsigned a0, unsigned a1, unsigned a2, unsigned a3,
                                         unsigned b0, unsigned b1) {
    asm volatile("mma.sync.aligned.m16n8k16.row.col.f32.bf16.bf16.f32 "
                 "{%0,%1,%2,%3}, {%4,%5,%6,%7}, {%8,%9}, {%0,%1,%2,%3};"
                 : "+f"(d[0]), "+f"(d[1]), "+f"(d[2]), "+f"(d[3])
                 : "r"(a0), "r"(a1), "r"(a2), "r"(a3), "r"(b0), "r"(b1));
}

// ---------------- prep: x = nodes * mask (float4) ----------------
__global__ void prep_x_kernel(const float* __restrict__ nodes,
                              const int* __restrict__ mask,
                              float* __restrict__ x) {
    int idx = blockIdx.x * 256 + threadIdx.x;
    int row = idx >> 5;
    float mi = mask[row] ? 1.f : 0.f;
    float4 v = ((const float4*)nodes)[idx];
    v.x *= mi; v.y *= mi; v.z *= mi; v.w *= mi;
    ((float4*)x)[idx] = v;
}

// cnt[b*N+i] = mask[b,i] * sum_j mask[b,j]
__global__ void prep_cnt_kernel(const int* __restrict__ mask,
                                float* __restrict__ cnt) {
    int b = blockIdx.x;
    int j = threadIdx.x;
    __shared__ float red[NN];
    float m = mask[b*NN + j] ? 1.f : 0.f;
    red[j] = m;
    __syncthreads();
    for (int s2 = 64; s2 > 0; s2 >>= 1) {
        if (j < s2) red[j] += red[j + s2];
        __syncthreads();
    }
    cnt[b*NN + j] = m * red[0];
}

// ---------------- copy uw1a rows into combined weight (float4) ----------------
__global__ void copy_uwc_kernel(const float* __restrict__ upd_w1,
                                float* __restrict__ uwc) {
    int l = blockIdx.y;
    int g = blockIdx.x * 256 + threadIdx.x;
    ((float4*)uwc)[(size_t)l*24576 + g] = ((const float4*)upd_w1)[(size_t)l*24576 + g];
}

// bb[l][n] = sum_k b2[l][k] * uw1[l][128+k][n]
__global__ void bb_kernel(const float* __restrict__ msg_b2,
                          const float* __restrict__ upd_w1,
                          float* __restrict__ bb) {
    int n = blockIdx.x;
    int l = blockIdx.y;
    int k = threadIdx.x;
    __shared__ float red[HH];
    red[k] = msg_b2[l*HH + k] * upd_w1[(size_t)l*384*HH + (128 + k)*HH + n];
    __syncthreads();
    for (int s2 = 128; s2 > 0; s2 >>= 1) {
        if (k < s2) red[k] += red[k + s2];
        __syncthreads();
    }
    if (k == 0) bb[l*HH + n] = red[0];
}

// ---------------- bf16 tensor-core edge kernel (R11 layout, 3 blocks/SM) ------
// s[b,i,h] = m_i * sum_j m_j * relu( np[b,i,h] + b1[h] + sum_e E[j,e]*W[e,h] )
// 256 threads, 8 warps x 32 h-cols (NT=4). launch_bounds(256,3) caps regs at 85
// -> 24 warps/SM (3 blocks) for +50% latency hiding at identical work layout.
__global__ __launch_bounds__(256, 3)
void edge_msg_tc(const float* __restrict__ edges,
                 const float* __restrict__ We,    // (64,256)
                 const float* __restrict__ b1,    // (256)
                 const float* __restrict__ np,    // (ROWS,256)
                 const int* __restrict__ mask,
                 float* __restrict__ s_out) {
    __shared__ __align__(16) unsigned sE[128 * 36];  // bf16x2 words, stride 36
    __shared__ float smj[NN];

    int row = blockIdx.x;
    int b = row >> 7;
    int t = threadIdx.x;
    int w = t >> 5;
    int lane = t & 31;
    int hb = w * 32;
    int r = lane >> 2;
    int c = lane & 3;

    // ---- stage E tile (128 j-rows x 64 e) as packed bf16 pairs ----
    const float4* src = (const float4*)(edges + (size_t)row * NN * EE);
#pragma unroll
    for (int g = t; g < 2048; g += 256) {
        float4 v = src[g];
        int rr = g >> 4;
        int p0 = (g & 15) * 2;
        unsigned w0 = pk_bf2(v.x, v.y);
        unsigned w1 = pk_bf2(v.z, v.w);
        *(uint2*)&sE[rr * 36 + p0] = make_uint2(w0, w1);
    }
    if (t < NN) smj[t] = mask[b*NN + t] ? 1.f : 0.f;

    // ---- B fragments ----
    unsigned B0[4][4], B1[4][4];
#pragma unroll
    for (int nt = 0; nt < 4; nt++) {
        int col = hb + nt*8 + r;
#pragma unroll
        for (int kk = 0; kk < 4; kk++) {
            int e0 = kk*16 + 2*c;
            B0[nt][kk] = pk_bf2(We[(e0)     * HH + col], We[(e0 + 1) * HH + col]);
            B1[nt][kk] = pk_bf2(We[(e0 + 8) * HH + col], We[(e0 + 9) * HH + col]);
        }
    }

    float npv0[4], npv1[4];
#pragma unroll
    for (int nt = 0; nt < 4; nt++) {
        int h = hb + nt*8 + 2*c;
        npv0[nt] = np[(size_t)row*HH + h]     + b1[h];
        npv1[nt] = np[(size_t)row*HH + h + 1] + b1[h + 1];
    }

    float s0[4] = {0.f, 0.f, 0.f, 0.f};
    float s1[4] = {0.f, 0.f, 0.f, 0.f};

    __syncthreads();

#pragma unroll 1
    for (int m0 = 0; m0 < 8; m0++) {
        float acc[4][4];
#pragma unroll
        for (int nt = 0; nt < 4; nt++) {
            acc[nt][0] = 0.f; acc[nt][1] = 0.f; acc[nt][2] = 0.f; acc[nt][3] = 0.f;
        }
        int rbase0 = (m0*16 + r) * 36;
        int rbase1 = (m0*16 + r + 8) * 36;
#pragma unroll
        for (int kk = 0; kk < 4; kk++) {
            unsigned a0 = sE[rbase0 + kk*8 + c];
            unsigned a1 = sE[rbase1 + kk*8 + c];
            unsigned a2 = sE[rbase0 + kk*8 + c + 4];
            unsigned a3 = sE[rbase1 + kk*8 + c + 4];
#pragma unroll
            for (int nt = 0; nt < 4; nt++)
                mma_bf16(acc[nt], a0, a1, a2, a3, B0[nt][kk], B1[nt][kk]);
        }
        float mj0 = smj[m0*16 + r];
        float mj1 = smj[m0*16 + r + 8];
#pragma unroll
        for (int nt = 0; nt < 4; nt++) {
            s0[nt] += mj0 * fmaxf(acc[nt][0] + npv0[nt], 0.f)
                    + mj1 * fmaxf(acc[nt][2] + npv0[nt], 0.f);
            s1[nt] += mj0 * fmaxf(acc[nt][1] + npv1[nt], 0.f)
                    + mj1 * fmaxf(acc[nt][3] + npv1[nt], 0.f);
        }
    }

#pragma unroll
    for (int off = 4; off < 32; off <<= 1) {
#pragma unroll
        for (int nt = 0; nt < 4; nt++) {
            s0[nt] += __shfl_xor_sync(0xffffffffu, s0[nt], off);
            s1[nt] += __shfl_xor_sync(0xffffffffu, s1[nt], off);
        }
    }

    float mi = mask[row] ? 1.f : 0.f;
    if (lane < 4) {
#pragma unroll
        for (int nt = 0; nt < 4; nt++) {
            int h = hb + nt*8 + 2*lane;
            s_out[(size_t)row*HH + h]     = mi * s0[nt];
            s_out[(size_t)row*HH + h + 1] = mi * s1[nt];
        }
    }
}

// ---------------- 3xTF32 split tensor-core GEMM, 32x64 tiles, batched ---------
__global__ __launch_bounds__(128)
void gemm_tc(int M, int N, int K, int K1,
             const float* __restrict__ A, int lda,
             const float* __restrict__ A2, int lda2,
             const float* __restrict__ W, int ldw,
             const float* __restrict__ bias,
             const float* __restrict__ rowscale,
             const float* __restrict__ bias2,
             const int* __restrict__ maskrow,
             float* __restrict__ C, int ldc, int flags,
             size_t bsA, size_t bsW, size_t bsC) {
    __shared__ __align__(16) float sA[2][32 * 36];
    __shared__ __align__(16) float sB[2][32 * 72];

    A += bsA * blockIdx.z;
    W += bsW * blockIdx.z;
    C += bsC * blockIdx.z;

    int tid = threadIdx.x;
    int w = tid >> 5;
    int lane = tid & 31;
    int wm = w & 1, wn = w >> 1;
    int r = lane >> 2, c = lane & 3;

    int bm = blockIdx.y * 32, bn = blockIdx.x * 64;

    float acc[4][4];
#pragma unroll
    for (int nt = 0; nt < 4; nt++)
#pragma unroll
        for (int i = 0; i < 4; i++) acc[nt][i] = 0.f;

    float4 pa[2], pb[4];

#define PREFETCH(k0_) do {                                                   \
    _Pragma("unroll")                                                        \
    for (int q = 0; q < 2; q++) {                                            \
        int g = tid + q*128;                                                 \
        int row_ = g >> 3, col4 = (g & 7) * 4;                               \
        int gm = bm + row_, gk = (k0_) + col4;                               \
        if (A2 != nullptr && gk >= K1)                                       \
            pa[q] = *(const float4*)(A2 + (size_t)gm*lda2 + (gk - K1));      \
        else                                                                 \
            pa[q] = *(const float4*)(A + (size_t)gm*lda + gk);               \
    }                                                                        \
    _Pragma("unroll")                                                        \
    for (int q = 0; q < 4; q++) {                                            \
        int g = tid + q*128;                                                 \
        int row_ = g >> 4, col4 = (g & 15) * 4;                              \
        pb[q] = *(const float4*)(W + (size_t)((k0_) + row_)*ldw + bn + col4);\
    }                                                                        \
} while (0)

#define STORE_STAGE(s_) do {                                                 \
    _Pragma("unroll")                                                        \
    for (int q = 0; q < 2; q++) {                                            \
        int g = tid + q*128;                                                 \
        int row_ = g >> 3, col4 = (g & 7) * 4;                               \
        *(float4*)&sA[s_][row_*36 + col4] = pa[q];                           \
    }                                                                        \
    _Pragma("unroll")                                                        \
    for (int q = 0; q < 4; q++) {                                            \
        int g = tid + q*128;                                                 \
        int row_ = g >> 4, col4 = (g & 15) * 4;                              \
        *(float4*)&sB[s_][row_*72 + col4] = pb[q];                           \
    }                                                                        \
} while (0)

    PREFETCH(0);
    STORE_STAGE(0);
    __syncthreads();

    int s = 0;
    for (int k0 = 0; ; ) {
        bool haveNext = (k0 + 32 < K);
        if (haveNext) PREFETCH(k0 + 32);

#pragma unroll
        for (int kk = 0; kk < 4; kk++) {
            unsigned bh0[4], bl0[4], bh1[4], bl1[4];
#pragma unroll
            for (int nt = 0; nt < 4; nt++) {
                int col = wn*32 + nt*8 + r;
                tfsplit(sB[s][(kk*8 + c)     * 72 + col], bh0[nt], bl0[nt]);
                tfsplit(sB[s][(kk*8 + c + 4) * 72 + col], bh1[nt], bl1[nt]);
            }
            int row0 = (wm*16 + r) * 36;
            int row1 = (wm*16 + r + 8) * 36;
            unsigned ah0, al0, ah1, al1, ah2, al2, ah3, al3;
            tfsplit(sA[s][row0 + kk*8 + c],     ah0, al0);
            tfsplit(sA[s][row1 + kk*8 + c],     ah1, al1);
            tfsplit(sA[s][row0 + kk*8 + c + 4], ah2, al2);
            tfsplit(sA[s][row1 + kk*8 + c + 4], ah3, al3);
#pragma unroll
            for (int nt = 0; nt < 4; nt++) {
                mma_tf32(acc[nt], ah0, ah1, ah2, ah3, bh0[nt], bh1[nt]);
                mma_tf32(acc[nt], al0, al1, al2, al3, bh0[nt], bh1[nt]);
                mma_tf32(acc[nt], ah0, ah1, ah2, ah3, bl0[nt], bl1[nt]);
            }
        }

        k0 += 32;
        if (!haveNext) break;
        STORE_STAGE(s ^ 1);
        __syncthreads();
        s ^= 1;
    }
#undef PREFETCH
#undef STORE_STAGE

#pragma unroll
    for (int i2 = 0; i2 < 2; i2++) {
        int gm = bm + wm*16 + r + i2*8;
        float rs = (rowscale != nullptr) ? rowscale[gm] : 1.f;
        float mf = (flags & GMASK) ? (maskrow[gm] ? 1.f : 0.f) : 1.f;
#pragma unroll
        for (int nt = 0; nt < 4; nt++) {
#pragma unroll
            for (int j = 0; j < 2; j++) {
                int gn = bn + wn*32 + nt*8 + 2*c + j;
                float v = acc[nt][i2*2 + j];
                if (bias != nullptr) v += bias[gn];
                if (bias2 != nullptr) v += rs * bias2[gn];
                if (flags & GRELU) v = fmaxf(v, 0.f);
                v *= mf;
                C[(size_t)gm*ldc + gn] = v;
            }
        }
    }
}

// ---------------- fused u-GEMM + residual LayerNorm ----------------
__global__ __launch_bounds__(256)
void ugemm_ln(const float* __restrict__ u1,        // (ROWS,256)
              const float* __restrict__ uw2,       // (256,128)
              const float* __restrict__ ub2,       // (128)
              const int* __restrict__ mask,
              const float* __restrict__ lng,
              const float* __restrict__ lnb,
              float* __restrict__ x) {
    __shared__ __align__(16) float sA[2][16 * 36];
    __shared__ __align__(16) float sB[2][32 * 136];
    __shared__ float sU[16 * 132];

    int tid = threadIdx.x;
    int w = tid >> 5;
    int lane = tid & 31;
    int wn = w;
    int r = lane >> 2, c = lane & 3;
    int bm = blockIdx.x * 16;

    float acc[2][4];
#pragma unroll
    for (int nt = 0; nt < 2; nt++)
#pragma unroll
        for (int i = 0; i < 4; i++) acc[nt][i] = 0.f;

    float4 pa;  bool pav;
    float4 pb[4];

#define UPREFETCH(k0_) do {                                                  \
    pav = (tid < 128);                                                       \
    if (pav) {                                                               \
        int row_ = tid >> 3, col4 = (tid & 7) * 4;                           \
        pa = *(const float4*)(u1 + (size_t)(bm + row_)*HH + (k0_) + col4);   \
    }                                                                        \
    _Pragma("unroll")                                                        \
    for (int q = 0; q < 4; q++) {                                            \
        int g = tid + q*256;                                                 \
        int row_ = g >> 5, col4 = (g & 31) * 4;                              \
        pb[q] = *(const float4*)(uw2 + (size_t)((k0_) + row_)*DD + col4);    \
    }                                                                        \
} while (0)

#define USTORE(s_) do {                                                      \
    if (pav) {                                                               \
        int row_ = tid >> 3, col4 = (tid & 7) * 4;                           \
        *(float4*)&sA[s_][row_*36 + col4] = pa;                              \
    }                                                                        \
    _Pragma("unroll")                                                        \
    for (int q = 0; q < 4; q++) {                                            \
        int g = tid + q*256;                                                 \
        int row_ = g >> 5, col4 = (g & 31) * 4;                              \
        *(float4*)&sB[s_][row_*136 + col4] = pb[q];                          \
    }                                                                        \
} while (0)

    UPREFETCH(0);
    USTORE(0);
    __syncthreads();

    int s = 0;
    for (int k0 = 0; ; ) {
        bool haveNext = (k0 + 32 < HH);
        if (haveNext) UPREFETCH(k0 + 32);

#pragma unroll
        for (int kk = 0; kk < 4; kk++) {
            unsigned bh0[2], bl0[2], bh1[2], bl1[2];
#pragma unroll
            for (int nt = 0; nt < 2; nt++) {
                int col = wn*16 + nt*8 + r;
                tfsplit(sB[s][(kk*8 + c)     * 136 + col], bh0[nt], bl0[nt]);
                tfsplit(sB[s][(kk*8 + c + 4) * 136 + col], bh1[nt], bl1[nt]);
            }
            int row0 = r * 36;
            int row1 = (r + 8) * 36;
            unsigned ah0, al0, ah1, al1, ah2, al2, ah3, al3;
            tfsplit(sA[s][row0 + kk*8 + c],     ah0, al0);
            tfsplit(sA[s][row1 + kk*8 + c],     ah1, al1);
            tfsplit(sA[s][row0 + kk*8 + c + 4], ah2, al2);
            tfsplit(sA[s][row1 + kk*8 + c + 4], ah3, al3);
#pragma unroll
            for (int nt = 0; nt < 2; nt++) {
                mma_tf32(acc[nt], ah0, ah1, ah2, ah3, bh0[nt], bh1[nt]);
                mma_tf32(acc[nt], al0, al1, al2, al3, bh0[nt], bh1[nt]);
                mma_tf32(acc[nt], ah0, ah1, ah2, ah3, bl0[nt], bl1[nt]);
            }
        }

        k0 += 32;
        if (!haveNext) break;
        USTORE(s ^ 1);
        __syncthreads();
        s ^= 1;
    }
#undef UPREFETCH
#undef USTORE

#pragma unroll
    for (int i2 = 0; i2 < 2; i2++) {
        int rr = r + i2*8;
#pragma unroll
        for (int nt = 0; nt < 2; nt++) {
#pragma unroll
            for (int j = 0; j < 2; j++) {
                int col = wn*16 + nt*8 + 2*c + j;
                sU[rr*132 + col] = acc[nt][i2*2 + j] + ub2[col];
            }
        }
    }
    __syncthreads();

#pragma unroll
    for (int q0 = 0; q0 < 2; q0++) {
        int rr = w*2 + q0;
        int row = bm + rr;
        float mi = mask[row] ? 1.f : 0.f;
        float v[4];
#pragma unroll
        for (int q = 0; q < 4; q++) {
            int d = lane + q*32;
            v[q] = x[(size_t)row*DD + d] + sU[rr*132 + d] * mi;
        }
        float sum = v[0] + v[1] + v[2] + v[3];
#pragma unroll
        for (int o = 16; o > 0; o >>= 1) sum += __shfl_xor_sync(0xffffffffu, sum, o);
        float mu = sum * (1.f / DD);
        float var = 0.f;
#pragma unroll
        for (int q = 0; q < 4; q++) { float d2 = v[q] - mu; var += d2*d2; }
#pragma unroll
        for (int o = 16; o > 0; o >>= 1) var += __shfl_xor_sync(0xffffffffu, var, o);
        float rstd = rsqrtf(var * (1.f / DD) + EPSLN);
#pragma unroll
        for (int q = 0; q < 4; q++) {
            int d = lane + q*32;
            x[(size_t)row*DD + d] = ((v[q] - mu) * rstd * lng[d] + lnb[d]) * mi;
        }
    }
}

// ---------------- host launch ----------------
extern "C" void kernel_launch(void* const* d_in, const int* in_sizes, int n_in,
                              void* d_out, int out_size) {
    const float* nodes  = (const float*)d_in[0];
    const float* edges  = (const float*)d_in[1];
    const int*   mask   = (const int*)d_in[2];
    const float* msg_w1 = (const float*)d_in[3];
    const float* msg_b1 = (const float*)d_in[4];
    const float* msg_w2 = (const float*)d_in[5];
    const float* msg_b2 = (const float*)d_in[6];
    const float* upd_w1 = (const float*)d_in[7];
    const float* upd_b1 = (const float*)d_in[8];
    const float* upd_w2 = (const float*)d_in[9];
    const float* upd_b2 = (const float*)d_in[10];
    const float* ln_g   = (const float*)d_in[11];
    const float* ln_b   = (const float*)d_in[12];
    const float* out_w1 = (const float*)d_in[13];
    const float* out_b1 = (const float*)d_in[14];
    const float* out_w2 = (const float*)d_in[15];
    const float* out_b2 = (const float*)d_in[16];
    float* out = (float*)d_out;

    float *x, *np, *s, *u1, *cnt, *uwc, *bb;
    cudaGetSymbolAddress((void**)&x,   g_x);
    cudaGetSymbolAddress((void**)&np,  g_np);
    cudaGetSymbolAddress((void**)&s,   g_s);
    cudaGetSymbolAddress((void**)&u1,  g_u1);
    cudaGetSymbolAddress((void**)&cnt, g_cnt);
    cudaGetSymbolAddress((void**)&uwc, g_uwc);
    cudaGetSymbolAddress((void**)&bb,  g_bb);

    // ---- per-launch weight precompute (input-independent) ----
    copy_uwc_kernel<<<dim3(32, 3), 256>>>(upd_w1, uwc);
    gemm_tc<<<dim3(HH/64, 256/32, 3), 128>>>(256, HH, HH, 0,
        msg_w2, HH, nullptr, 0,
        upd_w1 + 128*HH, HH,
        nullptr, nullptr, nullptr, nullptr,
        uwc + 128*HH, HH, 0,
        (size_t)HH*HH, (size_t)384*HH, (size_t)384*HH);
    bb_kernel<<<dim3(HH, 3), 256>>>(msg_b2, upd_w1, bb);

    prep_x_kernel<<<256, 256>>>(nodes, mask, x);
    prep_cnt_kernel<<<BATCH, NN>>>(mask, cnt);

    for (int l = 0; l < 3; l++) {
        const float* w1n = msg_w1 + (size_t)l * 192 * HH;
        const float* w1e = w1n + (size_t)DD * HH;
        const float* b1  = msg_b1 + (size_t)l * HH;
        const float* ub1 = upd_b1 + (size_t)l * HH;
        const float* uw2 = upd_w2 + (size_t)l * HH * DD;
        const float* ub2 = upd_b2 + (size_t)l * DD;
        const float* lg  = ln_g + (size_t)l * DD;
        const float* lb  = ln_b + (size_t)l * DD;

        // np = x @ w1n
        gemm_tc<<<dim3(HH/64, ROWS/32), 128>>>(ROWS, HH, DD, 0,
            x, DD, nullptr, 0, w1n, HH, nullptr, nullptr, nullptr, nullptr,
            np, HH, 0, 0, 0, 0);

        // s = masked relu-reduce of (np + edges@w1e + b1)  [bf16 tensor cores]
        edge_msg_tc<<<ROWS, 256>>>(edges, w1e, b1, np, mask, s);

        // u1 = relu([x|s] @ [uw1a;W2u] + ub1 + cnt*bb)
        gemm_tc<<<dim3(HH/64, ROWS/32), 128>>>(ROWS, HH, DD + HH, DD,
            x, DD, s, HH, uwc + (size_t)l*384*HH, HH,
            ub1, cnt, bb + (size_t)l*HH, nullptr, u1, HH, GRELU, 0, 0, 0);

        // u = u1@uw2 + ub2 fused with x = LN(x + u*mi)*mi
        ugemm_ln<<<ROWS/16, 256>>>(u1, uw2, ub2, mask, lg, lb, x);
    }

    // z = relu(x @ out_w1 + out_b1) -> u1
    gemm_tc<<<dim3(HH/64, ROWS/32), 128>>>(ROWS, HH, DD, 0,
        x, DD, nullptr, 0, out_w1, HH, out_b1, nullptr, nullptr, nullptr,
        u1, HH, GRELU, 0, 0, 0);

    // out = (z @ out_w2 + out_b2) * mask
    gemm_tc<<<dim3(DD/64, ROWS/32), 128>>>(ROWS, DD, HH, 0,
        u1, HH, nullptr, 0, out_w2, DD, out_b2, nullptr, nullptr, mask,
        out, DD, GMASK, 0, 0, 0);
}